// round 3
// baseline (speedup 1.0000x reference)
#include <cuda_runtime.h>
#include <cstdint>
#include <math.h>

// Problem constants
#define BB 8
#define LL 8192
#define CC 512
#define HH 8
#define WS 32
#define SHIFT 16
#define MLPD 2048
#define NW (LL / WS)          // 256 windows per batch
#define NTOK (BB * LL)        // 65536 tokens
#define HD (CC / HH)          // 64 head dim

// ---------------- scratch (device globals; allocation-free) ----------------
__device__ float g_h   [(size_t)NTOK * CC];      // LN1(x) rolled        134MB
__device__ float g_qkv [(size_t)NTOK * 3 * CC];  // qkv projections      402MB
__device__ float g_att [(size_t)NTOK * CC];      // attention output     134MB
__device__ float g_y   [(size_t)NTOK * CC];      // residual stream      134MB
__device__ float g_h2  [(size_t)NTOK * CC];      // LN2(y)               134MB
__device__ float g_mid [(size_t)NTOK * MLPD];    // GELU(fc1)            537MB

// ---------------- LayerNorm (optionally reading rolled-by-+SHIFT row) ------
__global__ __launch_bounds__(128) void ln_kernel(
    const float* __restrict__ in, const float* __restrict__ g,
    const float* __restrict__ be, float* __restrict__ out, int rolled)
{
    int row = blockIdx.x;                 // 0..NTOK-1 (output row)
    int b   = row >> 13;                  // /8192
    int l   = row & (LL - 1);
    int lsrc = rolled ? ((l + SHIFT) & (LL - 1)) : l;
    const float* src = in + ((size_t)((b << 13) | lsrc)) * CC;

    int tid = threadIdx.x;                // 128 threads, 4 floats each
    float4 v = reinterpret_cast<const float4*>(src)[tid];
    float s1 = v.x + v.y + v.z + v.w;
    float s2 = v.x*v.x + v.y*v.y + v.z*v.z + v.w*v.w;
    #pragma unroll
    for (int off = 16; off > 0; off >>= 1) {
        s1 += __shfl_down_sync(0xffffffffu, s1, off);
        s2 += __shfl_down_sync(0xffffffffu, s2, off);
    }
    __shared__ float sh1[4], sh2[4];
    int wid = tid >> 5, lane = tid & 31;
    if (lane == 0) { sh1[wid] = s1; sh2[wid] = s2; }
    __syncthreads();
    float t1 = sh1[0] + sh1[1] + sh1[2] + sh1[3];
    float t2 = sh2[0] + sh2[1] + sh2[2] + sh2[3];
    float mean = t1 * (1.0f / CC);
    float var  = t2 * (1.0f / CC) - mean * mean;
    float inv  = rsqrtf(var + 1e-5f);

    int c = tid * 4;
    float4 gg = reinterpret_cast<const float4*>(g)[tid];
    float4 bb = reinterpret_cast<const float4*>(be)[tid];
    float4 r;
    r.x = (v.x - mean) * inv * gg.x + bb.x;
    r.y = (v.y - mean) * inv * gg.y + bb.y;
    r.z = (v.z - mean) * inv * gg.z + bb.z;
    r.w = (v.w - mean) * inv * gg.w + bb.w;
    reinterpret_cast<float4*>(out + (size_t)row * CC)[tid] = r;
    (void)c;
}

// ---------------- windowed double-softmax attention ------------------------
// grid = (B*nW, H), block = 32 threads (one warp), thread x owns query row x.
__global__ __launch_bounds__(32) void attn_kernel(
    const float* __restrict__ qkv, const float* __restrict__ rel_table,
    float* __restrict__ out)
{
    __shared__ float qs[WS][HD], ks[WS][HD], vs[WS][HD];
    __shared__ float rel[2 * WS - 1];

    int w = blockIdx.x;          // global window (b*nW + wi)
    int h = blockIdx.y;
    int x = threadIdx.x;

    const float* base = qkv + (size_t)w * WS * (3 * CC) + h * HD;
    // cooperative load: per (matrix,row) 64 floats -> 32 threads x float2
    #pragma unroll 4
    for (int y = 0; y < WS; ++y) {
        const float2* qrow = reinterpret_cast<const float2*>(base + (size_t)y * 3 * CC);
        const float2* krow = reinterpret_cast<const float2*>(base + (size_t)y * 3 * CC + CC);
        const float2* vrow = reinterpret_cast<const float2*>(base + (size_t)y * 3 * CC + 2 * CC);
        reinterpret_cast<float2*>(qs[y])[x] = qrow[x];
        reinterpret_cast<float2*>(ks[y])[x] = krow[x];
        reinterpret_cast<float2*>(vs[y])[x] = vrow[x];
    }
    if (x < 2 * WS - 1) rel[x] = rel_table[x * HH + h];
    if (x + 32 < 2 * WS - 1) rel[x + 32] = rel_table[(x + 32) * HH + h];
    __syncthreads();

    const float scale = 0.125f;  // 64^-0.5
    float s[WS];
    const float4* qx = reinterpret_cast<const float4*>(qs[x]);
    #pragma unroll 4
    for (int y = 0; y < WS; ++y) {
        const float4* ky = reinterpret_cast<const float4*>(ks[y]);
        float acc = 0.f;
        #pragma unroll
        for (int i = 0; i < HD / 4; ++i) {
            float4 a = qx[i], b = ky[i];
            acc += a.x * b.x + a.y * b.y + a.z * b.z + a.w * b.w;
        }
        s[y] = acc * scale;
    }
    // softmax #1
    float mx = -1e30f;
    #pragma unroll
    for (int y = 0; y < WS; ++y) mx = fmaxf(mx, s[y]);
    float sum = 0.f;
    #pragma unroll
    for (int y = 0; y < WS; ++y) { s[y] = __expf(s[y] - mx); sum += s[y]; }
    float isum = 1.0f / sum;
    // + rel bias + shift mask, softmax #2
    int wi = w & (NW - 1);
    bool lastw = (wi == NW - 1);
    int px = wi * WS + x;
    int segx = (px >= LL - SHIFT) ? 2 : ((px >= LL - WS) ? 1 : 0);
    #pragma unroll
    for (int y = 0; y < WS; ++y) {
        float t = s[y] * isum + rel[x - y + WS - 1];
        if (lastw) {
            int py = wi * WS + y;
            int segy = (py >= LL - SHIFT) ? 2 : ((py >= LL - WS) ? 1 : 0);
            if (segy != segx) t -= 100.0f;
        }
        s[y] = t;
    }
    mx = -1e30f;
    #pragma unroll
    for (int y = 0; y < WS; ++y) mx = fmaxf(mx, s[y]);
    sum = 0.f;
    #pragma unroll
    for (int y = 0; y < WS; ++y) { s[y] = __expf(s[y] - mx); sum += s[y]; }
    isum = 1.0f / sum;

    // o[x,:] = att @ v
    float4 o[HD / 4];
    #pragma unroll
    for (int i = 0; i < HD / 4; ++i) o[i] = make_float4(0.f, 0.f, 0.f, 0.f);
    #pragma unroll 4
    for (int y = 0; y < WS; ++y) {
        float a = s[y] * isum;
        const float4* vy = reinterpret_cast<const float4*>(vs[y]);
        #pragma unroll
        for (int i = 0; i < HD / 4; ++i) {
            float4 vv = vy[i];
            o[i].x += a * vv.x; o[i].y += a * vv.y;
            o[i].z += a * vv.z; o[i].w += a * vv.w;
        }
    }
    float* orow = out + (size_t)(w * WS + x) * CC + h * HD;
    #pragma unroll
    for (int i = 0; i < HD / 4; ++i)
        reinterpret_cast<float4*>(orow)[i] = o[i];
}

// ---------------- SGEMM NT: out[m,n] = sum_k A[m,k]*W[n,k] + epilogue ------
// A: MxK row-major, W: NxK row-major. M%128==0, N%128==0, K%16==0.
#define EPI_NONE 0
#define EPI_ATTN 1   // out[unrolled idx] = extra[idx] + acc + bias[n]
#define EPI_GELU 2   // out = gelu(acc + bias[n])
#define EPI_RES  3   // out = extra[m*N+n] + acc + bias[n]

template <int EPI>
__global__ __launch_bounds__(256) void sgemm(
    const float* __restrict__ A, const float* __restrict__ W,
    const float* __restrict__ bias, float* __restrict__ out,
    const float* __restrict__ extra, int M, int N, int K)
{
    __shared__ float As[16][132];
    __shared__ float Bs[16][132];

    int tx = threadIdx.x & 15;
    int ty = threadIdx.x >> 4;
    int bm = blockIdx.y * 128;
    int bn = blockIdx.x * 128;

    float acc[8][8];
    #pragma unroll
    for (int i = 0; i < 8; ++i)
        #pragma unroll
        for (int j = 0; j < 8; ++j) acc[i][j] = 0.f;

    int lrow = threadIdx.x >> 2;        // 0..63
    int lc4  = (threadIdx.x & 3) * 4;   // 0,4,8,12
    const float* Ab = A + (size_t)(bm + lrow) * K + lc4;
    const float* Wb = W + (size_t)(bn + lrow) * K + lc4;
    size_t strideA = (size_t)64 * K;

    for (int k0 = 0; k0 < K; k0 += 16) {
        float4 a0 = *reinterpret_cast<const float4*>(Ab + k0);
        float4 a1 = *reinterpret_cast<const float4*>(Ab + strideA + k0);
        float4 b0 = *reinterpret_cast<const float4*>(Wb + k0);
        float4 b1 = *reinterpret_cast<const float4*>(Wb + strideA + k0);
        __syncthreads();
        As[lc4 + 0][lrow] = a0.x; As[lc4 + 1][lrow] = a0.y;
        As[lc4 + 2][lrow] = a0.z; As[lc4 + 3][lrow] = a0.w;
        As[lc4 + 0][lrow + 64] = a1.x; As[lc4 + 1][lrow + 64] = a1.y;
        As[lc4 + 2][lrow + 64] = a1.z; As[lc4 + 3][lrow + 64] = a1.w;
        Bs[lc4 + 0][lrow] = b0.x; Bs[lc4 + 1][lrow] = b0.y;
        Bs[lc4 + 2][lrow] = b0.z; Bs[lc4 + 3][lrow] = b0.w;
        Bs[lc4 + 0][lrow + 64] = b1.x; Bs[lc4 + 1][lrow + 64] = b1.y;
        Bs[lc4 + 2][lrow + 64] = b1.z; Bs[lc4 + 3][lrow + 64] = b1.w;
        __syncthreads();
        #pragma unroll
        for (int kk = 0; kk < 16; ++kk) {
            float4 a0v = *reinterpret_cast<const float4*>(&As[kk][ty * 4]);
            float4 a1v = *reinterpret_cast<const float4*>(&As[kk][64 + ty * 4]);
            float4 b0v = *reinterpret_cast<const float4*>(&Bs[kk][tx * 4]);
            float4 b1v = *reinterpret_cast<const float4*>(&Bs[kk][64 + tx * 4]);
            float ar[8] = {a0v.x, a0v.y, a0v.z, a0v.w, a1v.x, a1v.y, a1v.z, a1v.w};
            float br[8] = {b0v.x, b0v.y, b0v.z, b0v.w, b1v.x, b1v.y, b1v.z, b1v.w};
            #pragma unroll
            for (int i = 0; i < 8; ++i)
                #pragma unroll
                for (int j = 0; j < 8; ++j)
                    acc[i][j] += ar[i] * br[j];
        }
    }

    // epilogue
    #pragma unroll
    for (int i = 0; i < 8; ++i) {
        int m = bm + ((i < 4) ? (ty * 4 + i) : (60 + ty * 4 + i));
        #pragma unroll
        for (int jh = 0; jh < 2; ++jh) {
            int n = bn + jh * 64 + tx * 4;
            float v0 = acc[i][jh * 4 + 0], v1 = acc[i][jh * 4 + 1];
            float v2 = acc[i][jh * 4 + 2], v3 = acc[i][jh * 4 + 3];
            if (EPI == EPI_NONE) {
                float4 r = make_float4(v0, v1, v2, v3);
                *reinterpret_cast<float4*>(out + (size_t)m * N + n) = r;
            } else if (EPI == EPI_ATTN) {
                int b = m >> 13;
                int l = ((m & (LL - 1)) + SHIFT) & (LL - 1);
                size_t idx = ((size_t)((b << 13) | l)) * CC + n;
                float4 xr = *reinterpret_cast<const float4*>(extra + idx);
                float4 br4 = *reinterpret_cast<const float4*>(bias + n);
                float4 r = make_float4(xr.x + v0 + br4.x, xr.y + v1 + br4.y,
                                       xr.z + v2 + br4.z, xr.w + v3 + br4.w);
                *reinterpret_cast<float4*>(out + idx) = r;
            } else if (EPI == EPI_GELU) {
                float4 br4 = *reinterpret_cast<const float4*>(bias + n);
                float a0g = v0 + br4.x, a1g = v1 + br4.y;
                float a2g = v2 + br4.z, a3g = v3 + br4.w;
                float4 r;
                r.x = 0.5f * a0g * (1.0f + erff(a0g * 0.70710678118654752f));
                r.y = 0.5f * a1g * (1.0f + erff(a1g * 0.70710678118654752f));
                r.z = 0.5f * a2g * (1.0f + erff(a2g * 0.70710678118654752f));
                r.w = 0.5f * a3g * (1.0f + erff(a3g * 0.70710678118654752f));
                *reinterpret_cast<float4*>(out + (size_t)m * N + n) = r;
            } else {  // EPI_RES
                size_t idx = (size_t)m * N + n;
                float4 yr = *reinterpret_cast<const float4*>(extra + idx);
                float4 br4 = *reinterpret_cast<const float4*>(bias + n);
                float4 r = make_float4(yr.x + v0 + br4.x, yr.y + v1 + br4.y,
                                       yr.z + v2 + br4.z, yr.w + v3 + br4.w);
                *reinterpret_cast<float4*>(out + idx) = r;
            }
        }
    }
}

// ---------------- launch ---------------------------------------------------
extern "C" void kernel_launch(void* const* d_in, const int* in_sizes, int n_in,
                              void* d_out, int out_size)
{
    const float* x      = (const float*)d_in[0];
    const float* w_qkv  = (const float*)d_in[1];
    const float* w_out  = (const float*)d_in[2];
    const float* b_out  = (const float*)d_in[3];
    const float* rel_tb = (const float*)d_in[4];
    const float* g1     = (const float*)d_in[5];
    const float* be1    = (const float*)d_in[6];
    const float* g2     = (const float*)d_in[7];
    const float* be2    = (const float*)d_in[8];
    const float* w_fc1  = (const float*)d_in[9];
    const float* b_fc1  = (const float*)d_in[10];
    const float* w_fc2  = (const float*)d_in[11];
    const float* b_fc2  = (const float*)d_in[12];
    float* out = (float*)d_out;

    float *h, *qkv, *att, *y, *h2, *mid;
    cudaGetSymbolAddress((void**)&h,   g_h);
    cudaGetSymbolAddress((void**)&qkv, g_qkv);
    cudaGetSymbolAddress((void**)&att, g_att);
    cudaGetSymbolAddress((void**)&y,   g_y);
    cudaGetSymbolAddress((void**)&h2,  g_h2);
    cudaGetSymbolAddress((void**)&mid, g_mid);

    // 1. h = roll(LN1(x), -SHIFT)
    ln_kernel<<<NTOK, 128>>>(x, g1, be1, h, 1);
    // 2. qkv = h @ w_qkv^T
    sgemm<EPI_NONE><<<dim3(3 * CC / 128, NTOK / 128), 256>>>(
        h, w_qkv, nullptr, qkv, nullptr, NTOK, 3 * CC, CC);
    // 3. windowed attention (double softmax, rel bias, shift mask)
    attn_kernel<<<dim3(BB * NW, HH), 32>>>(qkv, rel_tb, att);
    // 4. y = x + roll(att @ w_out^T + b_out, +SHIFT)
    sgemm<EPI_ATTN><<<dim3(CC / 128, NTOK / 128), 256>>>(
        att, w_out, b_out, y, x, NTOK, CC, CC);
    // 5. h2 = LN2(y)
    ln_kernel<<<NTOK, 128>>>(y, g2, be2, h2, 0);
    // 6. mid = gelu(h2 @ w_fc1^T + b_fc1)
    sgemm<EPI_GELU><<<dim3(MLPD / 128, NTOK / 128), 256>>>(
        h2, w_fc1, b_fc1, mid, nullptr, NTOK, MLPD, CC);
    // 7. out = y + mid @ w_fc2^T + b_fc2
    sgemm<EPI_RES><<<dim3(CC / 128, NTOK / 128), 256>>>(
        mid, w_fc2, b_fc2, out, y, NTOK, CC, MLPD);
}

// round 6
// speedup vs baseline: 1.7552x; 1.7552x over previous
#include <cuda_runtime.h>
#include <cstdint>
#include <math.h>

// Problem constants
#define BB 8
#define LL 8192
#define CC 512
#define HH 8
#define WS 32
#define SHIFT 16
#define MLPD 2048
#define NW (LL / WS)          // 256 windows per batch
#define NTOK (BB * LL)        // 65536 tokens
#define HD (CC / HH)          // 64 head dim

// ---------------- scratch (device globals; allocation-free) ----------------
__device__ float g_h   [(size_t)NTOK * CC];
__device__ float g_qkv [(size_t)NTOK * 3 * CC];
__device__ float g_att [(size_t)NTOK * CC];
__device__ float g_y   [(size_t)NTOK * CC];
__device__ float g_h2  [(size_t)NTOK * CC];
__device__ float g_mid [(size_t)NTOK * MLPD];
// tf32-rounded weight copies
__device__ float g_wq  [3 * CC * CC];
__device__ float g_wo  [CC * CC];
__device__ float g_w1  [MLPD * CC];
__device__ float g_w2  [CC * MLPD];

__device__ __forceinline__ float tf32r(float x) {
    uint32_t u;
    asm("cvt.rna.tf32.f32 %0, %1;" : "=r"(u) : "f"(x));
    return __uint_as_float(u);
}

// ---------------- weight rounding (tiny, once per launch) ------------------
__global__ __launch_bounds__(256) void round_tf32_kernel(
    const float* __restrict__ in, float* __restrict__ out, int n4)
{
    int i = blockIdx.x * blockDim.x + threadIdx.x;
    if (i < n4) {
        float4 v = reinterpret_cast<const float4*>(in)[i];
        v.x = tf32r(v.x); v.y = tf32r(v.y); v.z = tf32r(v.z); v.w = tf32r(v.w);
        reinterpret_cast<float4*>(out)[i] = v;
    }
}

// ---------------- LayerNorm (optionally rolled); output tf32-rounded -------
__global__ __launch_bounds__(128) void ln_kernel(
    const float* __restrict__ in, const float* __restrict__ g,
    const float* __restrict__ be, float* __restrict__ out, int rolled)
{
    int row = blockIdx.x;
    int b   = row >> 13;
    int l   = row & (LL - 1);
    int lsrc = rolled ? ((l + SHIFT) & (LL - 1)) : l;
    const float* src = in + ((size_t)((b << 13) | lsrc)) * CC;

    int tid = threadIdx.x;
    float4 v = reinterpret_cast<const float4*>(src)[tid];
    float s1 = v.x + v.y + v.z + v.w;
    float s2 = v.x*v.x + v.y*v.y + v.z*v.z + v.w*v.w;
    #pragma unroll
    for (int off = 16; off > 0; off >>= 1) {
        s1 += __shfl_down_sync(0xffffffffu, s1, off);
        s2 += __shfl_down_sync(0xffffffffu, s2, off);
    }
    __shared__ float sh1[4], sh2[4];
    int wid = tid >> 5, lane = tid & 31;
    if (lane == 0) { sh1[wid] = s1; sh2[wid] = s2; }
    __syncthreads();
    float t1 = sh1[0] + sh1[1] + sh1[2] + sh1[3];
    float t2 = sh2[0] + sh2[1] + sh2[2] + sh2[3];
    float mean = t1 * (1.0f / CC);
    float var  = t2 * (1.0f / CC) - mean * mean;
    float inv  = rsqrtf(var + 1e-5f);

    float4 gg = reinterpret_cast<const float4*>(g)[tid];
    float4 bb = reinterpret_cast<const float4*>(be)[tid];
    float4 r;
    r.x = tf32r((v.x - mean) * inv * gg.x + bb.x);
    r.y = tf32r((v.y - mean) * inv * gg.y + bb.y);
    r.z = tf32r((v.z - mean) * inv * gg.z + bb.z);
    r.w = tf32r((v.w - mean) * inv * gg.w + bb.w);
    reinterpret_cast<float4*>(out + (size_t)row * CC)[tid] = r;
}

// ---------------- windowed double-softmax attention ------------------------
__global__ __launch_bounds__(32) void attn_kernel(
    const float* __restrict__ qkv, const float* __restrict__ rel_table,
    float* __restrict__ out)
{
    __shared__ float qs[WS][HD], ks[WS][HD], vs[WS][HD];
    __shared__ float rel[2 * WS - 1];

    int w = blockIdx.x;
    int h = blockIdx.y;
    int x = threadIdx.x;

    const float* base = qkv + (size_t)w * WS * (3 * CC) + h * HD;
    #pragma unroll 4
    for (int y = 0; y < WS; ++y) {
        const float2* qrow = reinterpret_cast<const float2*>(base + (size_t)y * 3 * CC);
        const float2* krow = reinterpret_cast<const float2*>(base + (size_t)y * 3 * CC + CC);
        const float2* vrow = reinterpret_cast<const float2*>(base + (size_t)y * 3 * CC + 2 * CC);
        reinterpret_cast<float2*>(qs[y])[x] = qrow[x];
        reinterpret_cast<float2*>(ks[y])[x] = krow[x];
        reinterpret_cast<float2*>(vs[y])[x] = vrow[x];
    }
    if (x < 2 * WS - 1) rel[x] = rel_table[x * HH + h];
    if (x + 32 < 2 * WS - 1) rel[x + 32] = rel_table[(x + 32) * HH + h];
    __syncthreads();

    const float scale = 0.125f;
    float s[WS];
    const float4* qx = reinterpret_cast<const float4*>(qs[x]);
    #pragma unroll 4
    for (int y = 0; y < WS; ++y) {
        const float4* ky = reinterpret_cast<const float4*>(ks[y]);
        float acc = 0.f;
        #pragma unroll
        for (int i = 0; i < HD / 4; ++i) {
            float4 a = qx[i], b = ky[i];
            acc += a.x * b.x + a.y * b.y + a.z * b.z + a.w * b.w;
        }
        s[y] = acc * scale;
    }
    float mx = -1e30f;
    #pragma unroll
    for (int y = 0; y < WS; ++y) mx = fmaxf(mx, s[y]);
    float sum = 0.f;
    #pragma unroll
    for (int y = 0; y < WS; ++y) { s[y] = __expf(s[y] - mx); sum += s[y]; }
    float isum = 1.0f / sum;
    int wi = w & (NW - 1);
    bool lastw = (wi == NW - 1);
    int px = wi * WS + x;
    int segx = (px >= LL - SHIFT) ? 2 : ((px >= LL - WS) ? 1 : 0);
    #pragma unroll
    for (int y = 0; y < WS; ++y) {
        float t = s[y] * isum + rel[x - y + WS - 1];
        if (lastw) {
            int py = wi * WS + y;
            int segy = (py >= LL - SHIFT) ? 2 : ((py >= LL - WS) ? 1 : 0);
            if (segy != segx) t -= 100.0f;
        }
        s[y] = t;
    }
    mx = -1e30f;
    #pragma unroll
    for (int y = 0; y < WS; ++y) mx = fmaxf(mx, s[y]);
    sum = 0.f;
    #pragma unroll
    for (int y = 0; y < WS; ++y) { s[y] = __expf(s[y] - mx); sum += s[y]; }
    isum = 1.0f / sum;

    float4 o[HD / 4];
    #pragma unroll
    for (int i = 0; i < HD / 4; ++i) o[i] = make_float4(0.f, 0.f, 0.f, 0.f);
    #pragma unroll 4
    for (int y = 0; y < WS; ++y) {
        float a = s[y] * isum;
        const float4* vy = reinterpret_cast<const float4*>(vs[y]);
        #pragma unroll
        for (int i = 0; i < HD / 4; ++i) {
            float4 vv = vy[i];
            o[i].x += a * vv.x; o[i].y += a * vv.y;
            o[i].z += a * vv.z; o[i].w += a * vv.w;
        }
    }
    float* orow = out + (size_t)(w * WS + x) * CC + h * HD;
    #pragma unroll
    for (int i = 0; i < HD / 4; ++i) {
        float4 r = o[i];
        r.x = tf32r(r.x); r.y = tf32r(r.y); r.z = tf32r(r.z); r.w = tf32r(r.w);
        reinterpret_cast<float4*>(orow)[i] = r;
    }
}

// ---------------- tf32 tensor-core GEMM NT ---------------------------------
// out[m,n] = sum_k A[m,k]*W[n,k] (+ epilogue). A: MxK rm, W: NxK rm.
// Block 128x128, 8 warps (2x4), warp tile 64x32, K chunk 16, cp.async 2-buf.
#define EPI_NONE 0
#define EPI_ATTN 1   // out[rolled idx] = extra[idx] + acc + bias[n]
#define EPI_GELU 2   // out = tf32(gelu(acc + bias[n]))
#define EPI_RES  3   // out = extra[m*N+n] + acc + bias[n]

#define KCH 16
#define SROW 20     // 16 + 4 pad floats (5 quads -> conflict-free ldmatrix)

template <int EPI>
__global__ __launch_bounds__(256, 2) void tgemm(
    const float* __restrict__ A, const float* __restrict__ W,
    const float* __restrict__ bias, float* __restrict__ out,
    const float* __restrict__ extra, int M, int N, int K)
{
    __shared__ float As[2][128 * SROW];
    __shared__ float Bs[2][128 * SROW];

    const int tid  = threadIdx.x;
    const int lane = tid & 31;
    const int warp = tid >> 5;
    const int wm = warp >> 2, wn = warp & 3;
    const int bm = blockIdx.y * 128, bn = blockIdx.x * 128;

    // staging loader: row = tid/4 (+64), col4 = (tid%4)*4
    const int lr = tid >> 2;
    const int lc = (tid & 3) * 4;
    const float* gA = A + (size_t)(bm + lr) * K + lc;
    const float* gB = W + (size_t)(bn + lr) * K + lc;
    const size_t gstep = (size_t)64 * K;

    const uint32_t sA = (uint32_t)__cvta_generic_to_shared(&As[0][0]);
    const uint32_t sB = (uint32_t)__cvta_generic_to_shared(&Bs[0][0]);
    const uint32_t BUFB = 128 * SROW * 4;
    const uint32_t dstA = ((lr) * SROW + lc) * 4;
    const uint32_t dstA2 = ((lr + 64) * SROW + lc) * 4;

    // ldmatrix lane-address components
    const int rr  = lane & 7, grp = lane >> 3;
    const int ar = (grp & 1) ? 8 : 0, ac = (grp & 2) ? 4 : 0;
    const int br = (grp & 2) ? 8 : 0, bc = (grp & 1) ? 4 : 0;
    uint32_t aoff[4], boff[2];
    #pragma unroll
    for (int mt = 0; mt < 4; ++mt)
        aoff[mt] = (uint32_t)(((wm * 64 + mt * 16 + rr + ar) * SROW + ac) * 4);
    #pragma unroll
    for (int np = 0; np < 2; ++np)
        boff[np] = (uint32_t)(((wn * 32 + np * 16 + rr + br) * SROW + bc) * 4);

    float c[4][4][4];
    #pragma unroll
    for (int i = 0; i < 4; ++i)
        #pragma unroll
        for (int j = 0; j < 4; ++j)
            #pragma unroll
            for (int r = 0; r < 4; ++r) c[i][j][r] = 0.f;

    const int S = K / KCH;

    auto issue = [&](int s, int buf) {
        uint32_t da = sA + buf * BUFB, db = sB + buf * BUFB;
        const float* ga = gA + (size_t)s * KCH;
        const float* gb = gB + (size_t)s * KCH;
        asm volatile("cp.async.cg.shared.global [%0], [%1], 16;\n" :: "r"(da + dstA),  "l"(ga));
        asm volatile("cp.async.cg.shared.global [%0], [%1], 16;\n" :: "r"(da + dstA2), "l"(ga + gstep));
        asm volatile("cp.async.cg.shared.global [%0], [%1], 16;\n" :: "r"(db + dstA),  "l"(gb));
        asm volatile("cp.async.cg.shared.global [%0], [%1], 16;\n" :: "r"(db + dstA2), "l"(gb + gstep));
    };

    issue(0, 0);
    asm volatile("cp.async.commit_group;\n");

    for (int s = 0; s < S; ++s) {
        if (s + 1 < S) issue(s + 1, (s + 1) & 1);
        asm volatile("cp.async.commit_group;\n");
        if (s + 1 < S) asm volatile("cp.async.wait_group 1;\n");
        else           asm volatile("cp.async.wait_group 0;\n");
        __syncthreads();

        const uint32_t ab = sA + (s & 1) * BUFB;
        const uint32_t bb = sB + (s & 1) * BUFB;
        #pragma unroll
        for (int kk = 0; kk < 2; ++kk) {
            uint32_t a[4][4], b2[2][4];
            #pragma unroll
            for (int mt = 0; mt < 4; ++mt) {
                asm volatile("ldmatrix.sync.aligned.m8n8.x4.shared.b16 {%0,%1,%2,%3}, [%4];\n"
                    : "=r"(a[mt][0]), "=r"(a[mt][1]), "=r"(a[mt][2]), "=r"(a[mt][3])
                    : "r"(ab + aoff[mt] + kk * 32));
            }
            #pragma unroll
            for (int np = 0; np < 2; ++np) {
                asm volatile("ldmatrix.sync.aligned.m8n8.x4.shared.b16 {%0,%1,%2,%3}, [%4];\n"
                    : "=r"(b2[np][0]), "=r"(b2[np][1]), "=r"(b2[np][2]), "=r"(b2[np][3])
                    : "r"(bb + boff[np] + kk * 32));
            }
            #pragma unroll
            for (int mt = 0; mt < 4; ++mt) {
                #pragma unroll
                for (int nt = 0; nt < 4; ++nt) {
                    asm volatile(
                        "mma.sync.aligned.m16n8k8.row.col.f32.tf32.tf32.f32 "
                        "{%0,%1,%2,%3}, {%4,%5,%6,%7}, {%8,%9}, {%0,%1,%2,%3};\n"
                        : "+f"(c[mt][nt][0]), "+f"(c[mt][nt][1]),
                          "+f"(c[mt][nt][2]), "+f"(c[mt][nt][3])
                        : "r"(a[mt][0]), "r"(a[mt][1]), "r"(a[mt][2]), "r"(a[mt][3]),
                          "r"(b2[nt >> 1][(nt & 1) * 2]), "r"(b2[nt >> 1][(nt & 1) * 2 + 1]));
                }
            }
        }
        __syncthreads();
    }

    // ---------------- epilogue (float2 per C-frag half) ---------------
    const int mrow = lane >> 2;
    const int ncol = (lane & 3) * 2;
    #pragma unroll
    for (int mt = 0; mt < 4; ++mt) {
        #pragma unroll
        for (int half = 0; half < 2; ++half) {
            int m = bm + wm * 64 + mt * 16 + mrow + half * 8;
            #pragma unroll
            for (int nt = 0; nt < 4; ++nt) {
                int n = bn + wn * 32 + nt * 8 + ncol;
                float v0 = c[mt][nt][half * 2 + 0];
                float v1 = c[mt][nt][half * 2 + 1];
                if (EPI == EPI_NONE) {
                    float2 r = make_float2(v0, v1);
                    *reinterpret_cast<float2*>(out + (size_t)m * N + n) = r;
                } else if (EPI == EPI_ATTN) {
                    int b = m >> 13;
                    int l = ((m & (LL - 1)) + SHIFT) & (LL - 1);
                    size_t idx = ((size_t)((b << 13) | l)) * CC + n;
                    float2 xr = *reinterpret_cast<const float2*>(extra + idx);
                    float2 br = *reinterpret_cast<const float2*>(bias + n);
                    float2 r = make_float2(xr.x + v0 + br.x, xr.y + v1 + br.y);
                    *reinterpret_cast<float2*>(out + idx) = r;
                } else if (EPI == EPI_GELU) {
                    float2 br = *reinterpret_cast<const float2*>(bias + n);
                    float a0 = v0 + br.x, a1 = v1 + br.y;
                    float2 r;
                    r.x = tf32r(0.5f * a0 * (1.0f + erff(a0 * 0.70710678118654752f)));
                    r.y = tf32r(0.5f * a1 * (1.0f + erff(a1 * 0.70710678118654752f)));
                    *reinterpret_cast<float2*>(out + (size_t)m * N + n) = r;
                } else { // EPI_RES
                    size_t idx = (size_t)m * N + n;
                    float2 yr = *reinterpret_cast<const float2*>(extra + idx);
                    float2 br = *reinterpret_cast<const float2*>(bias + n);
                    float2 r = make_float2(yr.x + v0 + br.x, yr.y + v1 + br.y);
                    *reinterpret_cast<float2*>(out + idx) = r;
                }
            }
        }
    }
}

// ---------------- launch ---------------------------------------------------
extern "C" void kernel_launch(void* const* d_in, const int* in_sizes, int n_in,
                              void* d_out, int out_size)
{
    const float* x      = (const float*)d_in[0];
    const float* w_qkv  = (const float*)d_in[1];
    const float* w_out  = (const float*)d_in[2];
    const float* b_out  = (const float*)d_in[3];
    const float* rel_tb = (const float*)d_in[4];
    const float* g1     = (const float*)d_in[5];
    const float* be1    = (const float*)d_in[6];
    const float* g2     = (const float*)d_in[7];
    const float* be2    = (const float*)d_in[8];
    const float* w_fc1  = (const float*)d_in[9];
    const float* b_fc1  = (const float*)d_in[10];
    const float* w_fc2  = (const float*)d_in[11];
    const float* b_fc2  = (const float*)d_in[12];
    float* out = (float*)d_out;

    float *h, *qkv, *att, *y, *h2, *mid, *wq, *wo, *w1, *w2;
    cudaGetSymbolAddress((void**)&h,   g_h);
    cudaGetSymbolAddress((void**)&qkv, g_qkv);
    cudaGetSymbolAddress((void**)&att, g_att);
    cudaGetSymbolAddress((void**)&y,   g_y);
    cudaGetSymbolAddress((void**)&h2,  g_h2);
    cudaGetSymbolAddress((void**)&mid, g_mid);
    cudaGetSymbolAddress((void**)&wq,  g_wq);
    cudaGetSymbolAddress((void**)&wo,  g_wo);
    cudaGetSymbolAddress((void**)&w1,  g_w1);
    cudaGetSymbolAddress((void**)&w2,  g_w2);

    // 0. tf32-round weights into scratch (cheap, ensures rna rounding)
    round_tf32_kernel<<<(3 * CC * CC / 4 + 255) / 256, 256>>>(w_qkv, wq, 3 * CC * CC / 4);
    round_tf32_kernel<<<(CC * CC / 4 + 255) / 256, 256>>>(w_out, wo, CC * CC / 4);
    round_tf32_kernel<<<(MLPD * CC / 4 + 255) / 256, 256>>>(w_fc1, w1, MLPD * CC / 4);
    round_tf32_kernel<<<(CC * MLPD / 4 + 255) / 256, 256>>>(w_fc2, w2, CC * MLPD / 4);

    // 1. h = tf32(roll(LN1(x), -SHIFT))
    ln_kernel<<<NTOK, 128>>>(x, g1, be1, h, 1);
    // 2. qkv = h @ wq^T
    tgemm<EPI_NONE><<<dim3(3 * CC / 128, NTOK / 128), 256>>>(
        h, wq, nullptr, qkv, nullptr, NTOK, 3 * CC, CC);
    // 3. windowed attention (double softmax, rel bias, shift mask); att tf32-rounded
    attn_kernel<<<dim3(BB * NW, HH), 32>>>(qkv, rel_tb, att);
    // 4. y = x + roll(att @ wo^T + b_out, +SHIFT)
    tgemm<EPI_ATTN><<<dim3(CC / 128, NTOK / 128), 256>>>(
        att, wo, b_out, y, x, NTOK, CC, CC);
    // 5. h2 = tf32(LN2(y))
    ln_kernel<<<NTOK, 128>>>(y, g2, be2, h2, 0);
    // 6. mid = tf32(gelu(h2 @ w1^T + b_fc1))
    tgemm<EPI_GELU><<<dim3(MLPD / 128, NTOK / 128), 256>>>(
        h2, w1, b_fc1, mid, nullptr, NTOK, MLPD, CC);
    // 7. out = y + mid @ w2^T + b_fc2
    tgemm<EPI_RES><<<dim3(CC / 128, NTOK / 128), 256>>>(
        mid, w2, b_fc2, out, y, NTOK, CC, MLPD);
}

// round 8
// speedup vs baseline: 3.6731x; 2.0927x over previous
#include <cuda_runtime.h>
#include <cuda_fp16.h>
#include <cstdint>
#include <math.h>

// Problem constants
#define BB 8
#define LL 8192
#define CC 512
#define HH 8
#define WS 32
#define SHIFT 16
#define MLPD 2048
#define NW (LL / WS)
#define NTOK (BB * LL)
#define HD (CC / HH)

// ---------------- scratch (device globals; allocation-free) ----------------
__device__ __half g_h   [(size_t)NTOK * CC];        // LN1 out (half)   64MB
__device__ __half g_qkv [(size_t)NTOK * 3 * CC];    // qkv (half)      201MB
__device__ __half g_att [(size_t)NTOK * CC];        // attn out (half)  64MB
__device__ float  g_y   [(size_t)NTOK * CC];        // residual (fp32) 134MB
__device__ __half g_h2  [(size_t)NTOK * CC];        // LN2 out (half)   64MB
__device__ __half g_mid [(size_t)NTOK * MLPD];      // gelu(fc1) half  268MB
__device__ __half g_wq  [3 * CC * CC];
__device__ __half g_wo  [CC * CC];
__device__ __half g_w1  [MLPD * CC];
__device__ __half g_w2  [CC * MLPD];

// ---------------- weight conversion ------------------------------------------
__global__ __launch_bounds__(256) void f2h_kernel(
    const float* __restrict__ in, __half* __restrict__ out, int n4)
{
    int i = blockIdx.x * blockDim.x + threadIdx.x;
    if (i < n4) {
        float4 v = reinterpret_cast<const float4*>(in)[i];
        __half2 h0 = __floats2half2_rn(v.x, v.y);
        __half2 h1 = __floats2half2_rn(v.z, v.w);
        reinterpret_cast<__half2*>(out)[2 * i]     = h0;
        reinterpret_cast<__half2*>(out)[2 * i + 1] = h1;
    }
}

// ---------------- LayerNorm (fp32 in, half out; optional roll) --------------
__global__ __launch_bounds__(128) void ln_kernel(
    const float* __restrict__ in, const float* __restrict__ g,
    const float* __restrict__ be, __half* __restrict__ out, int rolled)
{
    int row = blockIdx.x;
    int b   = row >> 13;
    int l   = row & (LL - 1);
    int lsrc = rolled ? ((l + SHIFT) & (LL - 1)) : l;
    const float* src = in + ((size_t)((b << 13) | lsrc)) * CC;

    int tid = threadIdx.x;
    float4 v = reinterpret_cast<const float4*>(src)[tid];
    float s1 = v.x + v.y + v.z + v.w;
    float s2 = v.x*v.x + v.y*v.y + v.z*v.z + v.w*v.w;
    #pragma unroll
    for (int off = 16; off > 0; off >>= 1) {
        s1 += __shfl_down_sync(0xffffffffu, s1, off);
        s2 += __shfl_down_sync(0xffffffffu, s2, off);
    }
    __shared__ float sh1[4], sh2[4];
    int wid = tid >> 5, lane = tid & 31;
    if (lane == 0) { sh1[wid] = s1; sh2[wid] = s2; }
    __syncthreads();
    float t1 = sh1[0] + sh1[1] + sh1[2] + sh1[3];
    float t2 = sh2[0] + sh2[1] + sh2[2] + sh2[3];
    float mean = t1 * (1.0f / CC);
    float var  = t2 * (1.0f / CC) - mean * mean;
    float inv  = rsqrtf(var + 1e-5f);

    float4 gg = reinterpret_cast<const float4*>(g)[tid];
    float4 bb = reinterpret_cast<const float4*>(be)[tid];
    __half2 r0 = __floats2half2_rn((v.x - mean) * inv * gg.x + bb.x,
                                   (v.y - mean) * inv * gg.y + bb.y);
    __half2 r1 = __floats2half2_rn((v.z - mean) * inv * gg.z + bb.z,
                                   (v.w - mean) * inv * gg.w + bb.w);
    __half2* dst = reinterpret_cast<__half2*>(out + (size_t)row * CC);
    dst[2 * tid]     = r0;
    dst[2 * tid + 1] = r1;
}

// ---------------- windowed double-softmax attention (half I/O) --------------
__global__ __launch_bounds__(32) void attn_kernel(
    const __half* __restrict__ qkv, const float* __restrict__ rel_table,
    __half* __restrict__ out)
{
    __shared__ float qs[WS][HD], ks[WS][HD], vs[WS][HD];
    __shared__ float rel[2 * WS - 1];

    int w = blockIdx.x;
    int h = blockIdx.y;
    int x = threadIdx.x;

    const __half* base = qkv + (size_t)w * WS * (3 * CC) + h * HD;
    #pragma unroll 4
    for (int y = 0; y < WS; ++y) {
        const __half2* qrow = reinterpret_cast<const __half2*>(base + (size_t)y * 3 * CC);
        const __half2* krow = reinterpret_cast<const __half2*>(base + (size_t)y * 3 * CC + CC);
        const __half2* vrow = reinterpret_cast<const __half2*>(base + (size_t)y * 3 * CC + 2 * CC);
        float2 q = __half22float2(qrow[x]);
        float2 k = __half22float2(krow[x]);
        float2 vv = __half22float2(vrow[x]);
        qs[y][2 * x] = q.x;  qs[y][2 * x + 1] = q.y;
        ks[y][2 * x] = k.x;  ks[y][2 * x + 1] = k.y;
        vs[y][2 * x] = vv.x; vs[y][2 * x + 1] = vv.y;
    }
    if (x < 2 * WS - 1) rel[x] = rel_table[x * HH + h];
    if (x + 32 < 2 * WS - 1) rel[x + 32] = rel_table[(x + 32) * HH + h];
    __syncthreads();

    const float scale = 0.125f;
    float s[WS];
    const float4* qx = reinterpret_cast<const float4*>(qs[x]);
    #pragma unroll 4
    for (int y = 0; y < WS; ++y) {
        const float4* ky = reinterpret_cast<const float4*>(ks[y]);
        float acc = 0.f;
        #pragma unroll
        for (int i = 0; i < HD / 4; ++i) {
            float4 a = qx[i], b = ky[i];
            acc += a.x * b.x + a.y * b.y + a.z * b.z + a.w * b.w;
        }
        s[y] = acc * scale;
    }
    float mx = -1e30f;
    #pragma unroll
    for (int y = 0; y < WS; ++y) mx = fmaxf(mx, s[y]);
    float sum = 0.f;
    #pragma unroll
    for (int y = 0; y < WS; ++y) { s[y] = __expf(s[y] - mx); sum += s[y]; }
    float isum = 1.0f / sum;
    int wi = w & (NW - 1);
    bool lastw = (wi == NW - 1);
    int px = wi * WS + x;
    int segx = (px >= LL - SHIFT) ? 2 : ((px >= LL - WS) ? 1 : 0);
    #pragma unroll
    for (int y = 0; y < WS; ++y) {
        float t = s[y] * isum + rel[x - y + WS - 1];
        if (lastw) {
            int py = wi * WS + y;
            int segy = (py >= LL - SHIFT) ? 2 : ((py >= LL - WS) ? 1 : 0);
            if (segy != segx) t -= 100.0f;
        }
        s[y] = t;
    }
    mx = -1e30f;
    #pragma unroll
    for (int y = 0; y < WS; ++y) mx = fmaxf(mx, s[y]);
    sum = 0.f;
    #pragma unroll
    for (int y = 0; y < WS; ++y) { s[y] = __expf(s[y] - mx); sum += s[y]; }
    isum = 1.0f / sum;

    float4 o[HD / 4];
    #pragma unroll
    for (int i = 0; i < HD / 4; ++i) o[i] = make_float4(0.f, 0.f, 0.f, 0.f);
    #pragma unroll 4
    for (int y = 0; y < WS; ++y) {
        float a = s[y] * isum;
        const float4* vy = reinterpret_cast<const float4*>(vs[y]);
        #pragma unroll
        for (int i = 0; i < HD / 4; ++i) {
            float4 vv = vy[i];
            o[i].x += a * vv.x; o[i].y += a * vv.y;
            o[i].z += a * vv.z; o[i].w += a * vv.w;
        }
    }
    __half2* orow = reinterpret_cast<__half2*>(
        out + (size_t)(w * WS + x) * CC + h * HD);
    #pragma unroll
    for (int i = 0; i < HD / 4; ++i) {
        orow[2 * i]     = __floats2half2_rn(o[i].x, o[i].y);
        orow[2 * i + 1] = __floats2half2_rn(o[i].z, o[i].w);
    }
}

// ---------------- fp16 tensor-core GEMM NT ----------------------------------
// out[m,n] = sum_k A[m,k]*W[n,k] (+epilogue). A: MxK rm half, W: NxK rm half.
// Block 128x128, 8 warps (2x4), warp tile 64x32, K-stage 32 halves, 2 buffers.
#define EPI_NONE 0   // half out
#define EPI_ATTN 1   // float out: extra[rolled] + acc + bias
#define EPI_GELU 2   // half out: gelu(acc + bias)
#define EPI_RES  3   // float out: extra + acc + bias

#define KCH 32
#define SROW 40      // 32 + 8 pad halves (80B rows; conflict-free ldmatrix)

template <int EPI>
__global__ __launch_bounds__(256, 2) void hgemm(
    const __half* __restrict__ A, const __half* __restrict__ W,
    const float* __restrict__ bias, void* __restrict__ outv,
    const float* __restrict__ extra, int M, int N, int K)
{
    __shared__ __half As[2][128 * SROW];
    __shared__ __half Bs[2][128 * SROW];

    const int tid  = threadIdx.x;
    const int lane = tid & 31;
    const int warp = tid >> 5;
    const int wm = warp >> 2, wn = warp & 3;
    const int bm = blockIdx.y * 128, bn = blockIdx.x * 128;

    // staging: thread t -> row = t>>1, 16-half chunk = t&1 (two 16B cp.async)
    const int lr = tid >> 1;
    const int lc = (tid & 1) * 16;
    const __half* gA = A + (size_t)(bm + lr) * K + lc;
    const __half* gB = W + (size_t)(bn + lr) * K + lc;

    const uint32_t sA = (uint32_t)__cvta_generic_to_shared(&As[0][0]);
    const uint32_t sB = (uint32_t)__cvta_generic_to_shared(&Bs[0][0]);
    const uint32_t BUFB = 128 * SROW * 2;
    const uint32_t dst0 = (uint32_t)(lr * SROW + lc) * 2;

    // ldmatrix lane addressing
    const int rr  = lane & 7, grp = lane >> 3;
    const int mr = (grp & 1) * 8;      // row offset within 16
    const int kc = (grp >> 1) * 8;     // k offset (halves)
    uint32_t aoff[4], boff[2];
    #pragma unroll
    for (int mt = 0; mt < 4; ++mt)
        aoff[mt] = (uint32_t)(((wm * 64 + mt * 16 + mr + rr) * SROW + kc) * 2);
    #pragma unroll
    for (int np = 0; np < 2; ++np)
        boff[np] = (uint32_t)(((wn * 32 + np * 16 + mr + rr) * SROW + kc) * 2);

    float c[4][4][4];
    #pragma unroll
    for (int i = 0; i < 4; ++i)
        #pragma unroll
        for (int j = 0; j < 4; ++j)
            #pragma unroll
            for (int r = 0; r < 4; ++r) c[i][j][r] = 0.f;

    const int S = K / KCH;

    auto issue = [&](int s, int buf) {
        uint32_t da = sA + buf * BUFB + dst0;
        uint32_t db = sB + buf * BUFB + dst0;
        const __half* ga = gA + (size_t)s * KCH;
        const __half* gb = gB + (size_t)s * KCH;
        asm volatile("cp.async.cg.shared.global [%0], [%1], 16;" :: "r"(da),      "l"(ga));
        asm volatile("cp.async.cg.shared.global [%0], [%1], 16;" :: "r"(da + 16), "l"(ga + 8));
        asm volatile("cp.async.cg.shared.global [%0], [%1], 16;" :: "r"(db),      "l"(gb));
        asm volatile("cp.async.cg.shared.global [%0], [%1], 16;" :: "r"(db + 16), "l"(gb + 8));
    };

    issue(0, 0);
    asm volatile("cp.async.commit_group;");

    for (int s = 0; s < S; ++s) {
        if (s + 1 < S) issue(s + 1, (s + 1) & 1);
        asm volatile("cp.async.commit_group;");
        if (s + 1 < S) asm volatile("cp.async.wait_group 1;");
        else           asm volatile("cp.async.wait_group 0;");
        __syncthreads();

        const uint32_t ab = sA + (s & 1) * BUFB;
        const uint32_t bb = sB + (s & 1) * BUFB;
        #pragma unroll
        for (int kk = 0; kk < 2; ++kk) {
            uint32_t a[4][4], b2[2][4];
            #pragma unroll
            for (int mt = 0; mt < 4; ++mt) {
                asm volatile("ldmatrix.sync.aligned.m8n8.x4.shared.b16 {%0,%1,%2,%3}, [%4];"
                    : "=r"(a[mt][0]), "=r"(a[mt][1]), "=r"(a[mt][2]), "=r"(a[mt][3])
                    : "r"(ab + aoff[mt] + kk * 32));
            }
            #pragma unroll
            for (int np = 0; np < 2; ++np) {
                asm volatile("ldmatrix.sync.aligned.m8n8.x4.shared.b16 {%0,%1,%2,%3}, [%4];"
                    : "=r"(b2[np][0]), "=r"(b2[np][1]), "=r"(b2[np][2]), "=r"(b2[np][3])
                    : "r"(bb + boff[np] + kk * 32));
            }
            #pragma unroll
            for (int mt = 0; mt < 4; ++mt) {
                #pragma unroll
                for (int nt = 0; nt < 4; ++nt) {
                    asm volatile(
                        "mma.sync.aligned.m16n8k16.row.col.f32.f16.f16.f32 "
                        "{%0,%1,%2,%3}, {%4,%5,%6,%7}, {%8,%9}, {%0,%1,%2,%3};"
                        : "+f"(c[mt][nt][0]), "+f"(c[mt][nt][1]),
                          "+f"(c[mt][nt][2]), "+f"(c[mt][nt][3])
                        : "r"(a[mt][0]), "r"(a[mt][1]), "r"(a[mt][2]), "r"(a[mt][3]),
                          "r"(b2[nt >> 1][nt & 1]), "r"(b2[nt >> 1][2 + (nt & 1)]));
                }
            }
        }
        __syncthreads();
    }

    // ---------------- epilogue ----------------
    const int mrow = lane >> 2;
    const int ncol = (lane & 3) * 2;
    #pragma unroll
    for (int mt = 0; mt < 4; ++mt) {
        #pragma unroll
        for (int half = 0; half < 2; ++half) {
            int m = bm + wm * 64 + mt * 16 + mrow + half * 8;
            #pragma unroll
            for (int nt = 0; nt < 4; ++nt) {
                int n = bn + wn * 32 + nt * 8 + ncol;
                float v0 = c[mt][nt][half * 2 + 0];
                float v1 = c[mt][nt][half * 2 + 1];
                if (EPI == EPI_NONE) {
                    __half* out = (__half*)outv;
                    *reinterpret_cast<__half2*>(out + (size_t)m * N + n) =
                        __floats2half2_rn(v0, v1);
                } else if (EPI == EPI_ATTN) {
                    float* out = (float*)outv;
                    int b = m >> 13;
                    int l = ((m & (LL - 1)) + SHIFT) & (LL - 1);
                    size_t idx = ((size_t)((b << 13) | l)) * CC + n;
                    float2 xr = *reinterpret_cast<const float2*>(extra + idx);
                    float2 br = *reinterpret_cast<const float2*>(bias + n);
                    *reinterpret_cast<float2*>(out + idx) =
                        make_float2(xr.x + v0 + br.x, xr.y + v1 + br.y);
                } else if (EPI == EPI_GELU) {
                    __half* out = (__half*)outv;
                    float2 br = *reinterpret_cast<const float2*>(bias + n);
                    float a0 = v0 + br.x, a1 = v1 + br.y;
                    float g0 = 0.5f * a0 * (1.0f + erff(a0 * 0.70710678118654752f));
                    float g1 = 0.5f * a1 * (1.0f + erff(a1 * 0.70710678118654752f));
                    *reinterpret_cast<__half2*>(out + (size_t)m * N + n) =
                        __floats2half2_rn(g0, g1);
                } else { // EPI_RES
                    float* out = (float*)outv;
                    size_t idx = (size_t)m * N + n;
                    float2 yr = *reinterpret_cast<const float2*>(extra + idx);
                    float2 br = *reinterpret_cast<const float2*>(bias + n);
                    *reinterpret_cast<float2*>(out + idx) =
                        make_float2(yr.x + v0 + br.x, yr.y + v1 + br.y);
                }
            }
        }
    }
}

// ---------------- launch ----------------------------------------------------
extern "C" void kernel_launch(void* const* d_in, const int* in_sizes, int n_in,
                              void* d_out, int out_size)
{
    const float* x      = (const float*)d_in[0];
    const float* w_qkv  = (const float*)d_in[1];
    const float* w_out  = (const float*)d_in[2];
    const float* b_out  = (const float*)d_in[3];
    const float* rel_tb = (const float*)d_in[4];
    const float* g1     = (const float*)d_in[5];
    const float* be1    = (const float*)d_in[6];
    const float* g2     = (const float*)d_in[7];
    const float* be2    = (const float*)d_in[8];
    const float* w_fc1  = (const float*)d_in[9];
    const float* b_fc1  = (const float*)d_in[10];
    const float* w_fc2  = (const float*)d_in[11];
    const float* b_fc2  = (const float*)d_in[12];
    float* out = (float*)d_out;

    __half *h, *qkv, *att, *h2, *mid, *wq, *wo, *w1, *w2;
    float *y;
    cudaGetSymbolAddress((void**)&h,   g_h);
    cudaGetSymbolAddress((void**)&qkv, g_qkv);
    cudaGetSymbolAddress((void**)&att, g_att);
    cudaGetSymbolAddress((void**)&y,   g_y);
    cudaGetSymbolAddress((void**)&h2,  g_h2);
    cudaGetSymbolAddress((void**)&mid, g_mid);
    cudaGetSymbolAddress((void**)&wq,  g_wq);
    cudaGetSymbolAddress((void**)&wo,  g_wo);
    cudaGetSymbolAddress((void**)&w1,  g_w1);
    cudaGetSymbolAddress((void**)&w2,  g_w2);

    // 0. fp16 weight copies
    f2h_kernel<<<(3 * CC * CC / 4 + 255) / 256, 256>>>(w_qkv, wq, 3 * CC * CC / 4);
    f2h_kernel<<<(CC * CC / 4 + 255) / 256, 256>>>(w_out, wo, CC * CC / 4);
    f2h_kernel<<<(MLPD * CC / 4 + 255) / 256, 256>>>(w_fc1, w1, MLPD * CC / 4);
    f2h_kernel<<<(CC * MLPD / 4 + 255) / 256, 256>>>(w_fc2, w2, CC * MLPD / 4);

    // 1. h = half(roll(LN1(x), -SHIFT))
    ln_kernel<<<NTOK, 128>>>(x, g1, be1, h, 1);
    // 2. qkv = h @ wq^T   (half out)
    hgemm<EPI_NONE><<<dim3(3 * CC / 128, NTOK / 128), 256>>>(
        h, wq, nullptr, qkv, nullptr, NTOK, 3 * CC, CC);
    // 3. windowed attention (double softmax, rel bias, shift mask)
    attn_kernel<<<dim3(BB * NW, HH), 32>>>(qkv, rel_tb, att);
    // 4. y = x + roll(att @ wo^T + b_out, +SHIFT)   (float out)
    hgemm<EPI_ATTN><<<dim3(CC / 128, NTOK / 128), 256>>>(
        att, wo, b_out, y, x, NTOK, CC, CC);
    // 5. h2 = half(LN2(y))
    ln_kernel<<<NTOK, 128>>>(y, g2, be2, h2, 0);
    // 6. mid = half(gelu(h2 @ w1^T + b_fc1))
    hgemm<EPI_GELU><<<dim3(MLPD / 128, NTOK / 128), 256>>>(
        h2, w1, b_fc1, mid, nullptr, NTOK, MLPD, CC);
    // 7. out = y + mid @ w2^T + b_fc2   (float out)
    hgemm<EPI_RES><<<dim3(CC / 128, NTOK / 128), 256>>>(
        mid, w2, b_fc2, out, y, NTOK, CC, MLPD);
}

// round 9
// speedup vs baseline: 3.9724x; 1.0815x over previous
#include <cuda_runtime.h>
#include <cuda_fp16.h>
#include <cstdint>
#include <math.h>

// Problem constants
#define BB 8
#define LL 8192
#define CC 512
#define HH 8
#define WS 32
#define SHIFT 16
#define MLPD 2048
#define NW (LL / WS)
#define NTOK (BB * LL)
#define HD (CC / HH)

// ---------------- scratch (device globals; allocation-free) ----------------
__device__ __half g_h   [(size_t)NTOK * CC];
__device__ __half g_qkv [(size_t)NTOK * 3 * CC];
__device__ __half g_att [(size_t)NTOK * CC];
__device__ float  g_y   [(size_t)NTOK * CC];
__device__ __half g_h2  [(size_t)NTOK * CC];
__device__ __half g_mid [(size_t)NTOK * MLPD];
__device__ __half g_wq  [3 * CC * CC];
__device__ __half g_wo  [CC * CC];
__device__ __half g_w1  [MLPD * CC];
__device__ __half g_w2  [CC * MLPD];

// ---------------- weight conversion -----------------------------------------
__global__ __launch_bounds__(256) void f2h_kernel(
    const float* __restrict__ in, __half* __restrict__ out, int n4)
{
    int i = blockIdx.x * blockDim.x + threadIdx.x;
    if (i < n4) {
        float4 v = reinterpret_cast<const float4*>(in)[i];
        reinterpret_cast<__half2*>(out)[2 * i]     = __floats2half2_rn(v.x, v.y);
        reinterpret_cast<__half2*>(out)[2 * i + 1] = __floats2half2_rn(v.z, v.w);
    }
}

// ---------------- LayerNorm (fp32 in, half out; optional roll) --------------
__global__ __launch_bounds__(128) void ln_kernel(
    const float* __restrict__ in, const float* __restrict__ g,
    const float* __restrict__ be, __half* __restrict__ out, int rolled)
{
    int row = blockIdx.x;
    int b   = row >> 13;
    int l   = row & (LL - 1);
    int lsrc = rolled ? ((l + SHIFT) & (LL - 1)) : l;
    const float* src = in + ((size_t)((b << 13) | lsrc)) * CC;

    int tid = threadIdx.x;
    float4 v = reinterpret_cast<const float4*>(src)[tid];
    float s1 = v.x + v.y + v.z + v.w;
    float s2 = v.x*v.x + v.y*v.y + v.z*v.z + v.w*v.w;
    #pragma unroll
    for (int off = 16; off > 0; off >>= 1) {
        s1 += __shfl_down_sync(0xffffffffu, s1, off);
        s2 += __shfl_down_sync(0xffffffffu, s2, off);
    }
    __shared__ float sh1[4], sh2[4];
    int wid = tid >> 5, lane = tid & 31;
    if (lane == 0) { sh1[wid] = s1; sh2[wid] = s2; }
    __syncthreads();
    float t1 = sh1[0] + sh1[1] + sh1[2] + sh1[3];
    float t2 = sh2[0] + sh2[1] + sh2[2] + sh2[3];
    float mean = t1 * (1.0f / CC);
    float var  = t2 * (1.0f / CC) - mean * mean;
    float inv  = rsqrtf(var + 1e-5f);

    float4 gg = reinterpret_cast<const float4*>(g)[tid];
    float4 bb = reinterpret_cast<const float4*>(be)[tid];
    __half2* dst = reinterpret_cast<__half2*>(out + (size_t)row * CC);
    dst[2 * tid]     = __floats2half2_rn((v.x - mean) * inv * gg.x + bb.x,
                                         (v.y - mean) * inv * gg.y + bb.y);
    dst[2 * tid + 1] = __floats2half2_rn((v.z - mean) * inv * gg.z + bb.z,
                                         (v.w - mean) * inv * gg.w + bb.w);
}

// ---------------- windowed double-softmax attention (4 heads/block) ---------
// grid = (B*nW, HH/4), block = 128. Warp w handles head blockIdx.y*4 + w.
#define ATT_SLICE (3 * WS * HD + 64)          // floats per warp slice
#define ATT_SMEM  (4 * ATT_SLICE * 4)         // bytes

__global__ __launch_bounds__(128) void attn_kernel(
    const __half* __restrict__ qkv, const float* __restrict__ rel_table,
    __half* __restrict__ out)
{
    extern __shared__ float smf[];
    int w   = blockIdx.x;
    int wid = threadIdx.x >> 5;
    int x   = threadIdx.x & 31;
    int h   = blockIdx.y * 4 + wid;

    float* qs  = smf + wid * ATT_SLICE;       // [WS][HD]
    float* ks  = qs + WS * HD;
    float* vs  = ks + WS * HD;
    float* rel = vs + WS * HD;

    const __half* base = qkv + (size_t)w * WS * (3 * CC) + h * HD;
    #pragma unroll 4
    for (int y = 0; y < WS; ++y) {
        const __half2* qrow = reinterpret_cast<const __half2*>(base + (size_t)y * 3 * CC);
        const __half2* krow = reinterpret_cast<const __half2*>(base + (size_t)y * 3 * CC + CC);
        const __half2* vrow = reinterpret_cast<const __half2*>(base + (size_t)y * 3 * CC + 2 * CC);
        float2 q = __half22float2(qrow[x]);
        float2 k = __half22float2(krow[x]);
        float2 vv = __half22float2(vrow[x]);
        qs[y * HD + 2 * x] = q.x;  qs[y * HD + 2 * x + 1] = q.y;
        ks[y * HD + 2 * x] = k.x;  ks[y * HD + 2 * x + 1] = k.y;
        vs[y * HD + 2 * x] = vv.x; vs[y * HD + 2 * x + 1] = vv.y;
    }
    if (x < 2 * WS - 1) rel[x] = rel_table[x * HH + h];
    if (x + 32 < 2 * WS - 1) rel[x + 32] = rel_table[(x + 32) * HH + h];
    __syncwarp();

    const float scale = 0.125f;
    float s[WS];
    const float4* qx = reinterpret_cast<const float4*>(qs + x * HD);
    #pragma unroll 4
    for (int y = 0; y < WS; ++y) {
        const float4* ky = reinterpret_cast<const float4*>(ks + y * HD);
        float acc = 0.f;
        #pragma unroll
        for (int i = 0; i < HD / 4; ++i) {
            float4 a = qx[i], b = ky[i];
            acc += a.x * b.x + a.y * b.y + a.z * b.z + a.w * b.w;
        }
        s[y] = acc * scale;
    }
    float mx = -1e30f;
    #pragma unroll
    for (int y = 0; y < WS; ++y) mx = fmaxf(mx, s[y]);
    float sum = 0.f;
    #pragma unroll
    for (int y = 0; y < WS; ++y) { s[y] = __expf(s[y] - mx); sum += s[y]; }
    float isum = 1.0f / sum;
    int wi = w & (NW - 1);
    bool lastw = (wi == NW - 1);
    int px = wi * WS + x;
    int segx = (px >= LL - SHIFT) ? 2 : ((px >= LL - WS) ? 1 : 0);
    #pragma unroll
    for (int y = 0; y < WS; ++y) {
        float t = s[y] * isum + rel[x - y + WS - 1];
        if (lastw) {
            int py = wi * WS + y;
            int segy = (py >= LL - SHIFT) ? 2 : ((py >= LL - WS) ? 1 : 0);
            if (segy != segx) t -= 100.0f;
        }
        s[y] = t;
    }
    mx = -1e30f;
    #pragma unroll
    for (int y = 0; y < WS; ++y) mx = fmaxf(mx, s[y]);
    sum = 0.f;
    #pragma unroll
    for (int y = 0; y < WS; ++y) { s[y] = __expf(s[y] - mx); sum += s[y]; }
    isum = 1.0f / sum;

    float4 o[HD / 4];
    #pragma unroll
    for (int i = 0; i < HD / 4; ++i) o[i] = make_float4(0.f, 0.f, 0.f, 0.f);
    #pragma unroll 4
    for (int y = 0; y < WS; ++y) {
        float a = s[y] * isum;
        const float4* vy = reinterpret_cast<const float4*>(vs + y * HD);
        #pragma unroll
        for (int i = 0; i < HD / 4; ++i) {
            float4 vv = vy[i];
            o[i].x += a * vv.x; o[i].y += a * vv.y;
            o[i].z += a * vv.z; o[i].w += a * vv.w;
        }
    }
    __half2* orow = reinterpret_cast<__half2*>(
        out + (size_t)(w * WS + x) * CC + h * HD);
    #pragma unroll
    for (int i = 0; i < HD / 4; ++i) {
        orow[2 * i]     = __floats2half2_rn(o[i].x, o[i].y);
        orow[2 * i + 1] = __floats2half2_rn(o[i].z, o[i].w);
    }
}

// ---------------- fp16 tensor-core GEMM NT ----------------------------------
// Block 128x128, 8 warps (2x4), warp tile 64x32, K-stage 32 halves,
// 4-stage cp.async ring, ONE __syncthreads per stage.
#define EPI_NONE 0
#define EPI_ATTN 1
#define EPI_GELU 2
#define EPI_RES  3

#define KCH 32
#define SROW 40
#define NSTG 4
#define STGH (128 * SROW)            // halfs per A (or B) tile
#define STAGE_H (2 * STGH)           // A + B halfs per stage
#define HG_SMEM (NSTG * STAGE_H * 2) // bytes = 81920

template <int EPI>
__global__ __launch_bounds__(256) void hgemm(
    const __half* __restrict__ A, const __half* __restrict__ W,
    const float* __restrict__ bias, void* __restrict__ outv,
    const float* __restrict__ extra, int M, int N, int K)
{
    extern __shared__ __half sm[];

    const int tid  = threadIdx.x;
    const int lane = tid & 31;
    const int warp = tid >> 5;
    const int wm = warp >> 2, wn = warp & 3;
    const int bm = blockIdx.y * 128, bn = blockIdx.x * 128;

    const int lr = tid >> 1;
    const int lc = (tid & 1) * 16;
    const __half* gA = A + (size_t)(bm + lr) * K + lc;
    const __half* gB = W + (size_t)(bn + lr) * K + lc;

    const uint32_t sbase = (uint32_t)__cvta_generic_to_shared(sm);
    const uint32_t dst0  = (uint32_t)(lr * SROW + lc) * 2;

    const int rr  = lane & 7, grp = lane >> 3;
    const int mr = (grp & 1) * 8;
    const int kc = (grp >> 1) * 8;
    uint32_t aoff[4], boff[2];
    #pragma unroll
    for (int mt = 0; mt < 4; ++mt)
        aoff[mt] = (uint32_t)(((wm * 64 + mt * 16 + mr + rr) * SROW + kc) * 2);
    #pragma unroll
    for (int np = 0; np < 2; ++np)
        boff[np] = (uint32_t)(((wn * 32 + np * 16 + mr + rr) * SROW + kc) * 2);

    float c[4][4][4];
    #pragma unroll
    for (int i = 0; i < 4; ++i)
        #pragma unroll
        for (int j = 0; j < 4; ++j)
            #pragma unroll
            for (int r = 0; r < 4; ++r) c[i][j][r] = 0.f;

    const int S = K / KCH;

    auto issue = [&](int t) {
        uint32_t base = sbase + (uint32_t)(t & (NSTG - 1)) * STAGE_H * 2;
        uint32_t da = base + dst0;
        uint32_t db = base + STGH * 2 + dst0;
        const __half* ga = gA + (size_t)t * KCH;
        const __half* gb = gB + (size_t)t * KCH;
        asm volatile("cp.async.cg.shared.global [%0], [%1], 16;" :: "r"(da),      "l"(ga));
        asm volatile("cp.async.cg.shared.global [%0], [%1], 16;" :: "r"(da + 16), "l"(ga + 8));
        asm volatile("cp.async.cg.shared.global [%0], [%1], 16;" :: "r"(db),      "l"(gb));
        asm volatile("cp.async.cg.shared.global [%0], [%1], 16;" :: "r"(db + 16), "l"(gb + 8));
    };

    issue(0); asm volatile("cp.async.commit_group;");
    issue(1); asm volatile("cp.async.commit_group;");
    issue(2); asm volatile("cp.async.commit_group;");

    for (int s = 0; s < S; ++s) {
        asm volatile("cp.async.wait_group 2;");
        __syncthreads();
        int t = s + 3;
        if (t < S) issue(t);
        asm volatile("cp.async.commit_group;");

        const uint32_t base = sbase + (uint32_t)(s & (NSTG - 1)) * STAGE_H * 2;
        const uint32_t ab = base;
        const uint32_t bb = base + STGH * 2;
        #pragma unroll
        for (int kk = 0; kk < 2; ++kk) {
            uint32_t a[4][4], b2[2][4];
            #pragma unroll
            for (int mt = 0; mt < 4; ++mt) {
                asm volatile("ldmatrix.sync.aligned.m8n8.x4.shared.b16 {%0,%1,%2,%3}, [%4];"
                    : "=r"(a[mt][0]), "=r"(a[mt][1]), "=r"(a[mt][2]), "=r"(a[mt][3])
                    : "r"(ab + aoff[mt] + kk * 32));
            }
            #pragma unroll
            for (int np = 0; np < 2; ++np) {
                asm volatile("ldmatrix.sync.aligned.m8n8.x4.shared.b16 {%0,%1,%2,%3}, [%4];"
                    : "=r"(b2[np][0]), "=r"(b2[np][1]), "=r"(b2[np][2]), "=r"(b2[np][3])
                    : "r"(bb + boff[np] + kk * 32));
            }
            #pragma unroll
            for (int mt = 0; mt < 4; ++mt) {
                #pragma unroll
                for (int nt = 0; nt < 4; ++nt) {
                    asm volatile(
                        "mma.sync.aligned.m16n8k16.row.col.f32.f16.f16.f32 "
                        "{%0,%1,%2,%3}, {%4,%5,%6,%7}, {%8,%9}, {%0,%1,%2,%3};"
                        : "+f"(c[mt][nt][0]), "+f"(c[mt][nt][1]),
                          "+f"(c[mt][nt][2]), "+f"(c[mt][nt][3])
                        : "r"(a[mt][0]), "r"(a[mt][1]), "r"(a[mt][2]), "r"(a[mt][3]),
                          "r"(b2[nt >> 1][nt & 1]), "r"(b2[nt >> 1][2 + (nt & 1)]));
                }
            }
        }
    }

    // ---------------- epilogue ----------------
    const int mrow = lane >> 2;
    const int ncol = (lane & 3) * 2;
    #pragma unroll
    for (int mt = 0; mt < 4; ++mt) {
        #pragma unroll
        for (int half = 0; half < 2; ++half) {
            int m = bm + wm * 64 + mt * 16 + mrow + half * 8;
            #pragma unroll
            for (int nt = 0; nt < 4; ++nt) {
                int n = bn + wn * 32 + nt * 8 + ncol;
                float v0 = c[mt][nt][half * 2 + 0];
                float v1 = c[mt][nt][half * 2 + 1];
                if (EPI == EPI_NONE) {
                    __half* out = (__half*)outv;
                    *reinterpret_cast<__half2*>(out + (size_t)m * N + n) =
                        __floats2half2_rn(v0, v1);
                } else if (EPI == EPI_ATTN) {
                    float* out = (float*)outv;
                    int b = m >> 13;
                    int l = ((m & (LL - 1)) + SHIFT) & (LL - 1);
                    size_t idx = ((size_t)((b << 13) | l)) * CC + n;
                    float2 xr = *reinterpret_cast<const float2*>(extra + idx);
                    float2 br = *reinterpret_cast<const float2*>(bias + n);
                    *reinterpret_cast<float2*>(out + idx) =
                        make_float2(xr.x + v0 + br.x, xr.y + v1 + br.y);
                } else if (EPI == EPI_GELU) {
                    __half* out = (__half*)outv;
                    float2 br = *reinterpret_cast<const float2*>(bias + n);
                    float a0 = v0 + br.x, a1 = v1 + br.y;
                    float g0 = 0.5f * a0 * (1.0f + erff(a0 * 0.70710678118654752f));
                    float g1 = 0.5f * a1 * (1.0f + erff(a1 * 0.70710678118654752f));
                    *reinterpret_cast<__half2*>(out + (size_t)m * N + n) =
                        __floats2half2_rn(g0, g1);
                } else { // EPI_RES
                    float* out = (float*)outv;
                    size_t idx = (size_t)m * N + n;
                    float2 yr = *reinterpret_cast<const float2*>(extra + idx);
                    float2 br = *reinterpret_cast<const float2*>(bias + n);
                    *reinterpret_cast<float2*>(out + idx) =
                        make_float2(yr.x + v0 + br.x, yr.y + v1 + br.y);
                }
            }
        }
    }
}

// ---------------- launch ----------------------------------------------------
extern "C" void kernel_launch(void* const* d_in, const int* in_sizes, int n_in,
                              void* d_out, int out_size)
{
    const float* x      = (const float*)d_in[0];
    const float* w_qkv  = (const float*)d_in[1];
    const float* w_out  = (const float*)d_in[2];
    const float* b_out  = (const float*)d_in[3];
    const float* rel_tb = (const float*)d_in[4];
    const float* g1     = (const float*)d_in[5];
    const float* be1    = (const float*)d_in[6];
    const float* g2     = (const float*)d_in[7];
    const float* be2    = (const float*)d_in[8];
    const float* w_fc1  = (const float*)d_in[9];
    const float* b_fc1  = (const float*)d_in[10];
    const float* w_fc2  = (const float*)d_in[11];
    const float* b_fc2  = (const float*)d_in[12];
    float* out = (float*)d_out;

    __half *h, *qkv, *att, *h2, *mid, *wq, *wo, *w1, *w2;
    float *y;
    cudaGetSymbolAddress((void**)&h,   g_h);
    cudaGetSymbolAddress((void**)&qkv, g_qkv);
    cudaGetSymbolAddress((void**)&att, g_att);
    cudaGetSymbolAddress((void**)&y,   g_y);
    cudaGetSymbolAddress((void**)&h2,  g_h2);
    cudaGetSymbolAddress((void**)&mid, g_mid);
    cudaGetSymbolAddress((void**)&wq,  g_wq);
    cudaGetSymbolAddress((void**)&wo,  g_wo);
    cudaGetSymbolAddress((void**)&w1,  g_w1);
    cudaGetSymbolAddress((void**)&w2,  g_w2);

    cudaFuncSetAttribute(hgemm<EPI_NONE>, cudaFuncAttributeMaxDynamicSharedMemorySize, HG_SMEM);
    cudaFuncSetAttribute(hgemm<EPI_ATTN>, cudaFuncAttributeMaxDynamicSharedMemorySize, HG_SMEM);
    cudaFuncSetAttribute(hgemm<EPI_GELU>, cudaFuncAttributeMaxDynamicSharedMemorySize, HG_SMEM);
    cudaFuncSetAttribute(hgemm<EPI_RES>,  cudaFuncAttributeMaxDynamicSharedMemorySize, HG_SMEM);
    cudaFuncSetAttribute(attn_kernel,     cudaFuncAttributeMaxDynamicSharedMemorySize, ATT_SMEM);

    // 0. fp16 weight copies
    f2h_kernel<<<(3 * CC * CC / 4 + 255) / 256, 256>>>(w_qkv, wq, 3 * CC * CC / 4);
    f2h_kernel<<<(CC * CC / 4 + 255) / 256, 256>>>(w_out, wo, CC * CC / 4);
    f2h_kernel<<<(MLPD * CC / 4 + 255) / 256, 256>>>(w_fc1, w1, MLPD * CC / 4);
    f2h_kernel<<<(CC * MLPD / 4 + 255) / 256, 256>>>(w_fc2, w2, CC * MLPD / 4);

    // 1. h = half(roll(LN1(x), -SHIFT))
    ln_kernel<<<NTOK, 128>>>(x, g1, be1, h, 1);
    // 2. qkv = h @ wq^T
    hgemm<EPI_NONE><<<dim3(3 * CC / 128, NTOK / 128), 256, HG_SMEM>>>(
        h, wq, nullptr, qkv, nullptr, NTOK, 3 * CC, CC);
    // 3. windowed attention (4 heads per 128-thread block)
    attn_kernel<<<dim3(BB * NW, HH / 4), 128, ATT_SMEM>>>(qkv, rel_tb, att);
    // 4. y = x + roll(att @ wo^T + b_out, +SHIFT)
    hgemm<EPI_ATTN><<<dim3(CC / 128, NTOK / 128), 256, HG_SMEM>>>(
        att, wo, b_out, y, x, NTOK, CC, CC);
    // 5. h2 = half(LN2(y))
    ln_kernel<<<NTOK, 128>>>(y, g2, be2, h2, 0);
    // 6. mid = half(gelu(h2 @ w1^T + b_fc1))
    hgemm<EPI_GELU><<<dim3(MLPD / 128, NTOK / 128), 256, HG_SMEM>>>(
        h2, w1, b_fc1, mid, nullptr, NTOK, MLPD, CC);
    // 7. out = y + mid @ w2^T + b_fc2
    hgemm<EPI_RES><<<dim3(CC / 128, NTOK / 128), 256, HG_SMEM>>>(
        mid, w2, b_fc2, out, y, NTOK, CC, MLPD);
}